// round 16
// baseline (speedup 1.0000x reference)
#include <cuda_runtime.h>
#include <cuda_bf16.h>
#include <cstdint>

// Problem constants
#define BB 8
#define QQ 64
#define CC 512
#define DD 512
#define HH 256
#define EPSF 1e-5f
#define WOFF (BB * QQ * DD)

typedef unsigned long long ull;

__device__ float g_resq[BB * QQ * HH];        // [bq][h]
__device__ float g_rescT[BB * HH * CC];       // [b][h][c]

__device__ __forceinline__ float tanh_approx(float x) {
    float y;
    asm("tanh.approx.f32 %0, %1;" : "=f"(y) : "f"(x));
    return y;
}
__device__ __forceinline__ ull pack2(float x) {
    ull r; asm("mov.b64 %0, {%1, %1};" : "=l"(r) : "f"(x)); return r;
}
__device__ __forceinline__ void fma2(ull& d, ull a, ull b) {
    asm("fma.rn.f32x2 %0, %1, %2, %0;" : "+l"(d) : "l"(a), "l"(b));
}
__device__ __forceinline__ float2 unpack2(ull v) {
    float2 r; asm("mov.b64 {%0, %1}, %2;" : "=f"(r.x), "=f"(r.y) : "l"(v)); return r;
}
__device__ __forceinline__ uint32_t s2u(const void* p) {
    uint32_t a;
    asm("{ .reg .u64 t; cvta.to.shared.u64 t, %1; cvt.u32.u64 %0, t; }"
        : "=r"(a) : "l"(p));
    return a;
}
__device__ __forceinline__ void cp16(uint32_t s, const void* g) {
    asm volatile("cp.async.cg.shared.global [%0], [%1], 16;" :: "r"(s), "l"(g) : "memory");
}

#define MMA_TF32(c, a, b0, b1)                                            \
    asm volatile("mma.sync.aligned.m16n8k8.row.col.f32.tf32.tf32.f32 "    \
                 "{%0,%1,%2,%3}, {%4,%5,%6,%7}, {%8,%9}, {%0,%1,%2,%3};"  \
                 : "+f"((c)[0]), "+f"((c)[1]), "+f"((c)[2]), "+f"((c)[3]) \
                 : "r"((a)[0]), "r"((a)[1]), "r"((a)[2]), "r"((a)[3]),    \
                   "r"(b0), "r"(b1))

// ---- tc_gemms tiling: K-tile 64, 3 stages ----
#define LDA 72
#define ATILE_U (128 * LDA)
#define BTILE_U (64 * LDA)
#define STAGE_U (ATILE_U + BTILE_U)
#define NSTAGE 3
#define TCG_SMEM (NSTAGE * STAGE_U * 4)   // 165888 B

// ---------------------------------------------------------------------------
// A: tf32 mma.sync GEMMs, cp.async 3-stage pipeline, K-tile 64. 144 blocks x
// 256 threads (R14 config). Fragment loads SOFTWARE-PIPELINED: ks+1's LDS
// issue before ks's MMAs, hiding the 29-cyc LDS latency. Smem pointers hoisted.
// ---------------------------------------------------------------------------
__global__ __launch_bounds__(256, 1)
void tc_gemms(const float* __restrict__ Wc,
              const float* __restrict__ Ctx,
              const float* __restrict__ bc,
              const float* __restrict__ Qm,
              const float* __restrict__ Wq)
{
    extern __shared__ uint32_t smem[];
    const uint32_t smem_b = s2u(smem);

    const int tid  = threadIdx.x;
    const int wid  = tid >> 5;
    const int lane = tid & 31;
    const int g    = lane >> 2;
    const int tg   = lane & 3;

    const int mbase = (wid & 3) * 32;
    const int nbase = (wid >> 2) * 32;

    const float *Ap, *Bp;
    const float* biasp = nullptr;
    float* outp;
    int ldo;
    const int blk = blockIdx.x;
    if (blk < 128) {
        const int b  = blk >> 4;
        const int ht = (blk >> 3) & 1;
        const int ct = blk & 7;
        Ap    = Wc + (size_t)(ht * 128) * DD;
        Bp    = Ctx + (size_t)b * CC * DD + (size_t)(ct * 64) * DD;
        outp  = g_rescT + (size_t)b * HH * CC + (size_t)(ht * 128) * CC + ct * 64;
        ldo   = CC;
        biasp = bc + ht * 128;
    } else {
        const int blk2 = blk - 128;
        const int mt = blk2 >> 2;
        const int nt = blk2 & 3;
        Ap   = Qm + (size_t)(mt * 128) * DD;
        Bp   = Wq + (size_t)(nt * 64) * DD;
        outp = g_resq + (size_t)(mt * 128) * HH + nt * 64;
        ldo  = HH;
    }

    int am[8], ak[8], bm[4], bk[4];
    #pragma unroll
    for (int i = 0; i < 8; i++) {
        const int f = tid + (i << 8);
        am[i] = f >> 4;
        ak[i] = (f & 15) << 2;
    }
    #pragma unroll
    for (int i = 0; i < 4; i++) {
        const int f = tid + (i << 8);
        bm[i] = f >> 4;
        bk[i] = (f & 15) << 2;
    }

    auto issue_stage = [&](int buf, int kt) {
        const uint32_t base = smem_b + buf * (STAGE_U * 4);
        #pragma unroll
        for (int i = 0; i < 8; i++)
            cp16(base + (am[i] * LDA + ak[i]) * 4,
                 Ap + (size_t)am[i] * DD + kt + ak[i]);
        #pragma unroll
        for (int i = 0; i < 4; i++)
            cp16(base + (ATILE_U + bm[i] * LDA + bk[i]) * 4,
                 Bp + (size_t)bm[i] * DD + kt + bk[i]);
        asm volatile("cp.async.commit_group;" ::: "memory");
    };

    float acc[2][4][4] = {};

    issue_stage(0, 0);
    issue_stage(1, 64);

    const int foff = 2 * tg;

    // hoisted per-warp fragment row offsets (u32 elements)
    const int a_row0 = (mbase + g) * LDA + foff;          // mt=0 lo
    const int a_row1 = (mbase + 8 + g) * LDA + foff;      // mt=0 hi
    const int a_row2 = (mbase + 16 + g) * LDA + foff;     // mt=1 lo
    const int a_row3 = (mbase + 24 + g) * LDA + foff;     // mt=1 hi
    const int b_row0 = (nbase + g) * LDA + foff;
    const int b_row1 = (nbase + 8 + g) * LDA + foff;
    const int b_row2 = (nbase + 16 + g) * LDA + foff;
    const int b_row3 = (nbase + 24 + g) * LDA + foff;

    #pragma unroll 1
    for (int t = 0; t < 8; t++) {
        if (t < 6) {
            asm volatile("cp.async.wait_group 1;" ::: "memory");
        } else {
            asm volatile("cp.async.wait_group 0;" ::: "memory");
        }
        __syncthreads();

        if (t < 6) issue_stage((t + 2) % NSTAGE, (t + 2) * 64);

        const uint32_t* A_s = smem + (t % NSTAGE) * STAGE_U;
        const uint32_t* B_s = A_s + ATILE_U;

        // fragment register double-buffer
        uint2 fa[2][2][2];   // [buf][mt][lo/hi]
        uint2 fb[2][4];      // [buf][nt]

        // prologue: load ks=0 fragments
        fa[0][0][0] = *(const uint2*)&A_s[a_row0];
        fa[0][0][1] = *(const uint2*)&A_s[a_row1];
        fa[0][1][0] = *(const uint2*)&A_s[a_row2];
        fa[0][1][1] = *(const uint2*)&A_s[a_row3];
        fb[0][0] = *(const uint2*)&B_s[b_row0];
        fb[0][1] = *(const uint2*)&B_s[b_row1];
        fb[0][2] = *(const uint2*)&B_s[b_row2];
        fb[0][3] = *(const uint2*)&B_s[b_row3];

        #pragma unroll
        for (int ks = 0; ks < 8; ks++) {
            const int cur = ks & 1;
            const int nxt = cur ^ 1;
            if (ks < 7) {
                const int kc = (ks + 1) * 8;
                fa[nxt][0][0] = *(const uint2*)&A_s[a_row0 + kc];
                fa[nxt][0][1] = *(const uint2*)&A_s[a_row1 + kc];
                fa[nxt][1][0] = *(const uint2*)&A_s[a_row2 + kc];
                fa[nxt][1][1] = *(const uint2*)&A_s[a_row3 + kc];
                fb[nxt][0] = *(const uint2*)&B_s[b_row0 + kc];
                fb[nxt][1] = *(const uint2*)&B_s[b_row1 + kc];
                fb[nxt][2] = *(const uint2*)&B_s[b_row2 + kc];
                fb[nxt][3] = *(const uint2*)&B_s[b_row3 + kc];
            }
            #pragma unroll
            for (int mt = 0; mt < 2; mt++) {
                uint32_t a[4];
                a[0] = fa[cur][mt][0].x; a[2] = fa[cur][mt][0].y;
                a[1] = fa[cur][mt][1].x; a[3] = fa[cur][mt][1].y;
                #pragma unroll
                for (int nt = 0; nt < 4; nt++) {
                    MMA_TF32(acc[mt][nt], a, fb[cur][nt].x, fb[cur][nt].y);
                }
            }
        }
    }

    #pragma unroll
    for (int mt = 0; mt < 2; mt++) {
        const int row0 = mbase + mt * 16 + g;
        const int row1 = row0 + 8;
        const float bi0 = biasp ? biasp[row0] : 0.f;
        const float bi1 = biasp ? biasp[row1] : 0.f;
        #pragma unroll
        for (int nt = 0; nt < 4; nt++) {
            const int col = nbase + nt * 8 + tg * 2;
            float2 o0; o0.x = acc[mt][nt][0] + bi0; o0.y = acc[mt][nt][1] + bi0;
            float2 o1; o1.x = acc[mt][nt][2] + bi1; o1.y = acc[mt][nt][3] + bi1;
            *(float2*)(outp + (size_t)row0 * ldo + col) = o0;
            *(float2*)(outp + (size_t)row1 * ldo + col) = o1;
        }
    }
}

// ---------------------------------------------------------------------------
// B: logits (tanh over H) + softmax; writes weights to out[WOFF..].
// Best-measured version: q-tile 4, grid 128, 1024 threads, h-split halves.
// ---------------------------------------------------------------------------
__global__ __launch_bounds__(1024)
void logits_softmax(const float* __restrict__ Maskp,
                    const float* __restrict__ Wo,
                    const float* __restrict__ bo_p,
                    float* __restrict__ out)
{
    const int blk  = blockIdx.x;       // 0..127
    const int b    = blk >> 4;
    const int q0   = (blk & 15) * 4;
    const int tid  = threadIdx.x;
    const int c    = tid & 511;
    const int half = tid >> 9;

    __shared__ float4 sh_rq[HH];
    __shared__ float  sh_wo[HH];
    __shared__ float4 sh_acc[CC];
    __shared__ float  sh_part[4][16];
    __shared__ float  sh_tot[4];

    if (tid < HH) {
        float4 r;
        r.x = g_resq[(b * QQ + q0 + 0) * HH + tid];
        r.y = g_resq[(b * QQ + q0 + 1) * HH + tid];
        r.z = g_resq[(b * QQ + q0 + 2) * HH + tid];
        r.w = g_resq[(b * QQ + q0 + 3) * HH + tid];
        sh_rq[tid] = r;
        sh_wo[tid] = Wo[tid];
    }
    __syncthreads();

    float a0 = 0.f, a1 = 0.f, a2 = 0.f, a3 = 0.f;
    {
        const int hbase = half << 7;
        const float* rc = g_rescT + (size_t)b * HH * CC + (size_t)hbase * CC + c;
        #pragma unroll 8
        for (int h = 0; h < 128; h++) {
            const float  a  = rc[(size_t)h * CC];
            const float4 rq = sh_rq[hbase + h];
            const float  w  = sh_wo[hbase + h];
            a0 += w * tanh_approx(a + rq.x);
            a1 += w * tanh_approx(a + rq.y);
            a2 += w * tanh_approx(a + rq.z);
            a3 += w * tanh_approx(a + rq.w);
        }
    }
    if (half == 0) {
        sh_acc[c] = make_float4(a0, a1, a2, a3);
    }
    __syncthreads();

    float e0, e1, e2, e3;
    if (half == 1) {
        const float4 p = sh_acc[c];
        const float bo = __ldg(bo_p);
        const float m  = Maskp[b * CC + c];
        e0 = m * __expf(a0 + p.x + bo);
        e1 = m * __expf(a1 + p.y + bo);
        e2 = m * __expf(a2 + p.z + bo);
        e3 = m * __expf(a3 + p.w + bo);

        float s0 = e0, s1 = e1, s2 = e2, s3 = e3;
        #pragma unroll
        for (int off = 16; off > 0; off >>= 1) {
            s0 += __shfl_xor_sync(0xffffffffu, s0, off);
            s1 += __shfl_xor_sync(0xffffffffu, s1, off);
            s2 += __shfl_xor_sync(0xffffffffu, s2, off);
            s3 += __shfl_xor_sync(0xffffffffu, s3, off);
        }
        const int lane = tid & 31, w2 = (tid >> 5) & 15;
        if (lane == 0) {
            sh_part[0][w2] = s0; sh_part[1][w2] = s1;
            sh_part[2][w2] = s2; sh_part[3][w2] = s3;
        }
    }
    __syncthreads();
    if (tid < 4) {
        float t = 0.f;
        #pragma unroll
        for (int i = 0; i < 16; i++) t += sh_part[tid][i];
        sh_tot[tid] = 1.f / (t + EPSF);
    }
    __syncthreads();

    if (half == 1) {
        out[WOFF + (b * QQ + q0 + 0) * CC + c] = e0 * sh_tot[0];
        out[WOFF + (b * QQ + q0 + 1) * CC + c] = e1 * sh_tot[1];
        out[WOFF + (b * QQ + q0 + 2) * CC + c] = e2 * sh_tot[2];
        out[WOFF + (b * QQ + q0 + 3) * CC + c] = e3 * sh_tot[3];
    }
}

// ---------------------------------------------------------------------------
// C: output[bq][d] = sum_c weights[bq][c] * ctx[b][c][d]
// cp.async 3-stage pipeline, K(=c)-tile 64. 128 blocks x 256 thr. (R14)
// ---------------------------------------------------------------------------
#define OG_LDW 68
#define OG_LDC 36
#define OG_WS_U (64 * OG_LDW)
#define OG_CS_U (64 * OG_LDC)
#define OG_STAGE_U (OG_WS_U + OG_CS_U)
#define OG_SMEM (NSTAGE * OG_STAGE_U * 4)  // 79872 B

__global__ __launch_bounds__(256, 1)
void out_gemm(const float* __restrict__ Ctx,
              const float* __restrict__ Wgt,
              float* __restrict__ out)
{
    extern __shared__ uint32_t smem[];
    const uint32_t smem_b = s2u(smem);

    const int blk = blockIdx.x;        // 0..127
    const int b   = blk >> 4;
    const int d0  = (blk & 15) * 32;
    const int tid = threadIdx.x;
    const int ty  = tid >> 4;
    const int tx  = tid & 15;

    const float* Wp = Wgt + (size_t)b * QQ * CC;
    const float* Cp = Ctx + (size_t)b * CC * DD + d0;

    int wq[4], wc[4], cc_[2], cd[2];
    #pragma unroll
    for (int i = 0; i < 4; i++) {
        const int f = tid + (i << 8);
        wq[i] = f >> 4;
        wc[i] = (f & 15) << 2;
    }
    #pragma unroll
    for (int i = 0; i < 2; i++) {
        const int f = tid + (i << 8);
        cc_[i] = f >> 3;
        cd[i]  = (f & 7) << 2;
    }

    auto issue_stage = [&](int buf, int kt) {
        const uint32_t base = smem_b + buf * (OG_STAGE_U * 4);
        #pragma unroll
        for (int i = 0; i < 4; i++)
            cp16(base + (wq[i] * OG_LDW + wc[i]) * 4,
                 Wp + (size_t)wq[i] * CC + kt + wc[i]);
        #pragma unroll
        for (int i = 0; i < 2; i++)
            cp16(base + (OG_WS_U + cc_[i] * OG_LDC + cd[i]) * 4,
                 Cp + (size_t)(kt + cc_[i]) * DD + cd[i]);
        asm volatile("cp.async.commit_group;" ::: "memory");
    };

    ull acc[4] = {};

    issue_stage(0, 0);
    issue_stage(1, 64);

    #pragma unroll 1
    for (int t = 0; t < 8; t++) {
        if (t < 6) {
            asm volatile("cp.async.wait_group 1;" ::: "memory");
        } else {
            asm volatile("cp.async.wait_group 0;" ::: "memory");
        }
        __syncthreads();

        if (t < 6) issue_stage((t + 2) % NSTAGE, (t + 2) * 64);

        const float* W_s = (const float*)(smem + (t % NSTAGE) * OG_STAGE_U);
        const float* C_s = W_s + OG_WS_U;
        #pragma unroll 8
        for (int cc = 0; cc < 64; cc++) {
            const ull cv = *(const ull*)&C_s[cc * OG_LDC + tx * 2];
            const float w0 = W_s[(ty * 4 + 0) * OG_LDW + cc];
            const float w1 = W_s[(ty * 4 + 1) * OG_LDW + cc];
            const float w2 = W_s[(ty * 4 + 2) * OG_LDW + cc];
            const float w3 = W_s[(ty * 4 + 3) * OG_LDW + cc];
            fma2(acc[0], pack2(w0), cv);
            fma2(acc[1], pack2(w1), cv);
            fma2(acc[2], pack2(w2), cv);
            fma2(acc[3], pack2(w3), cv);
        }
    }

    #pragma unroll
    for (int i = 0; i < 4; i++) {
        float2 p = unpack2(acc[i]);
        const int q = ty * 4 + i;
        *(float2*)&out[(b * QQ + q) * DD + d0 + tx * 2] = p;
    }
}

// ---------------------------------------------------------------------------
extern "C" void kernel_launch(void* const* d_in, const int* in_sizes, int n_in,
                              void* d_out, int out_size)
{
    const float* query   = (const float*)d_in[0];
    const float* context = (const float*)d_in[1];
    const float* mask    = (const float*)d_in[2];
    const float* W_c     = (const float*)d_in[3];
    const float* b_c     = (const float*)d_in[4];
    const float* W_q     = (const float*)d_in[5];
    const float* W_o     = (const float*)d_in[6];
    const float* b_o     = (const float*)d_in[7];
    float* out = (float*)d_out;

    cudaFuncSetAttribute(tc_gemms, cudaFuncAttributeMaxDynamicSharedMemorySize,
                         TCG_SMEM);
    cudaFuncSetAttribute(out_gemm, cudaFuncAttributeMaxDynamicSharedMemorySize,
                         OG_SMEM);

    tc_gemms<<<144, 256, TCG_SMEM>>>(W_c, context, b_c, query, W_q);
    logits_softmax<<<128, 1024>>>(mask, W_o, b_o, out);
    out_gemm<<<128, 256, OG_SMEM>>>(context, out + WOFF, out);
}

// round 17
// speedup vs baseline: 1.0136x; 1.0136x over previous
#include <cuda_runtime.h>
#include <cuda_bf16.h>
#include <cstdint>

// Problem constants
#define BB 8
#define QQ 64
#define CC 512
#define DD 512
#define HH 256
#define EPSF 1e-5f
#define WOFF (BB * QQ * DD)

typedef unsigned long long ull;

__device__ float g_resq[BB * QQ * HH];        // [bq][h]
__device__ float g_rescT[BB * HH * CC];       // [b][h][c]

__device__ __forceinline__ float tanh_approx(float x) {
    float y;
    asm("tanh.approx.f32 %0, %1;" : "=f"(y) : "f"(x));
    return y;
}
__device__ __forceinline__ ull pack2(float x) {
    ull r; asm("mov.b64 %0, {%1, %1};" : "=l"(r) : "f"(x)); return r;
}
__device__ __forceinline__ void fma2(ull& d, ull a, ull b) {
    asm("fma.rn.f32x2 %0, %1, %2, %0;" : "+l"(d) : "l"(a), "l"(b));
}
__device__ __forceinline__ float2 unpack2(ull v) {
    float2 r; asm("mov.b64 {%0, %1}, %2;" : "=f"(r.x), "=f"(r.y) : "l"(v)); return r;
}
__device__ __forceinline__ uint32_t s2u(const void* p) {
    uint32_t a;
    asm("{ .reg .u64 t; cvta.to.shared.u64 t, %1; cvt.u32.u64 %0, t; }"
        : "=r"(a) : "l"(p));
    return a;
}
__device__ __forceinline__ void cp16(uint32_t s, const void* g) {
    asm volatile("cp.async.cg.shared.global [%0], [%1], 16;" :: "r"(s), "l"(g) : "memory");
}

#define MMA_TF32(c, a, b0, b1)                                            \
    asm volatile("mma.sync.aligned.m16n8k8.row.col.f32.tf32.tf32.f32 "    \
                 "{%0,%1,%2,%3}, {%4,%5,%6,%7}, {%8,%9}, {%0,%1,%2,%3};"  \
                 : "+f"((c)[0]), "+f"((c)[1]), "+f"((c)[2]), "+f"((c)[3]) \
                 : "r"((a)[0]), "r"((a)[1]), "r"((a)[2]), "r"((a)[3]),    \
                   "r"(b0), "r"(b1))

#define NSTAGE 3

// ---- tc_gemms tiling: 64x64 block tile, K-tile 32, 3 stages, 2 blocks/SM ----
#define LDA2 40                        // 32 k + 8 pad (u32)
#define T2_U (64 * LDA2)               // 2560 u32 per matrix tile
#define STAGE2_U (2 * T2_U)            // 5120 u32 per stage (A + B)
#define TCG_SMEM (NSTAGE * STAGE2_U * 4)   // 61440 B -> 2 blocks/SM

// ---------------------------------------------------------------------------
// A: tf32 mma.sync GEMMs. 64x64 tiles, grid 288 (2 blocks/SM: cross-block
// overlap hides stage waits that intra-block tricks could not). K-tile 32,
// cp.async 3-stage. 8 warps in 2x4; warp tile 32m x 16n (2x2 m16n8k8).
//   blocks [0,256):  res_cT[b]: D[m=h(64)][n=c(64)] = Wc[h,:]·ctx[b][c,:]+bias
//   blocks [256,288): res_q:    D[m=bq(64)][n=h(64)] = q[bq,:]·Wq[h,:]
// ---------------------------------------------------------------------------
__global__ __launch_bounds__(256, 2)
void tc_gemms(const float* __restrict__ Wc,
              const float* __restrict__ Ctx,
              const float* __restrict__ bc,
              const float* __restrict__ Qm,
              const float* __restrict__ Wq)
{
    extern __shared__ uint32_t smem[];
    const uint32_t smem_b = s2u(smem);

    const int tid  = threadIdx.x;
    const int wid  = tid >> 5;
    const int lane = tid & 31;
    const int g    = lane >> 2;
    const int tg   = lane & 3;

    const int mbase = (wid & 1) * 32;   // 2 warps over M=64
    const int nbase = (wid >> 1) * 16;  // 4 warps over N=64

    const float *Ap, *Bp;
    const float* biasp = nullptr;
    float* outp;
    int ldo;
    const int blk = blockIdx.x;
    if (blk < 256) {
        const int b  = blk >> 5;
        const int ht = (blk >> 3) & 3;
        const int ct = blk & 7;
        Ap    = Wc + (size_t)(ht * 64) * DD;
        Bp    = Ctx + (size_t)b * CC * DD + (size_t)(ct * 64) * DD;
        outp  = g_rescT + (size_t)b * HH * CC + (size_t)(ht * 64) * CC + ct * 64;
        ldo   = CC;
        biasp = bc + ht * 64;
    } else {
        const int blk2 = blk - 256;      // 0..31
        const int mt = blk2 >> 2;        // 0..7
        const int nt = blk2 & 3;         // 0..3
        Ap   = Qm + (size_t)(mt * 64) * DD;
        Bp   = Wq + (size_t)(nt * 64) * DD;
        outp = g_resq + (size_t)(mt * 64) * HH + nt * 64;
        ldo  = HH;
    }

    // staging coords: A 512 float4 (2/thread), B 512 float4 (2/thread)
    int am[2], ak[2];
    #pragma unroll
    for (int i = 0; i < 2; i++) {
        const int f = tid + (i << 8);
        am[i] = f >> 3;                  // row 0..63
        ak[i] = (f & 7) << 2;            // k offset 0..28
    }

    auto issue_stage = [&](int buf, int kt) {
        const uint32_t base = smem_b + buf * (STAGE2_U * 4);
        #pragma unroll
        for (int i = 0; i < 2; i++) {
            cp16(base + (am[i] * LDA2 + ak[i]) * 4,
                 Ap + (size_t)am[i] * DD + kt + ak[i]);
            cp16(base + (T2_U + am[i] * LDA2 + ak[i]) * 4,
                 Bp + (size_t)am[i] * DD + kt + ak[i]);
        }
        asm volatile("cp.async.commit_group;" ::: "memory");
    };

    float acc[2][2][4] = {};

    issue_stage(0, 0);
    issue_stage(1, 32);

    const int foff = 2 * tg;

    #pragma unroll 1
    for (int t = 0; t < 16; t++) {
        if (t < 14) {
            asm volatile("cp.async.wait_group 1;" ::: "memory");
        } else {
            asm volatile("cp.async.wait_group 0;" ::: "memory");
        }
        __syncthreads();

        if (t < 14) issue_stage((t + 2) % NSTAGE, (t + 2) * 32);

        const uint32_t* A_s = smem + (t % NSTAGE) * STAGE2_U;
        const uint32_t* B_s = A_s + T2_U;
        #pragma unroll
        for (int ks = 0; ks < 4; ks++) {
            const int kc = ks * 8 + foff;
            uint32_t a[2][4];
            #pragma unroll
            for (int mt = 0; mt < 2; mt++) {
                const int rbase = (mbase + mt * 16 + g) * LDA2 + kc;
                const uint2 lo = *(const uint2*)&A_s[rbase];             // a0, a2
                const uint2 hi = *(const uint2*)&A_s[rbase + 8 * LDA2];  // a1, a3
                a[mt][0] = lo.x; a[mt][2] = lo.y;
                a[mt][1] = hi.x; a[mt][3] = hi.y;
            }
            #pragma unroll
            for (int nt = 0; nt < 2; nt++) {
                const int bbase = (nbase + nt * 8 + g) * LDA2 + kc;
                const uint2 bv = *(const uint2*)&B_s[bbase];             // b0, b1
                MMA_TF32(acc[0][nt], a[0], bv.x, bv.y);
                MMA_TF32(acc[1][nt], a[1], bv.x, bv.y);
            }
        }
    }

    // Epilogue
    #pragma unroll
    for (int mt = 0; mt < 2; mt++) {
        const int row0 = mbase + mt * 16 + g;
        const int row1 = row0 + 8;
        const float bi0 = biasp ? biasp[row0] : 0.f;
        const float bi1 = biasp ? biasp[row1] : 0.f;
        #pragma unroll
        for (int nt = 0; nt < 2; nt++) {
            const int col = nbase + nt * 8 + tg * 2;
            float2 o0; o0.x = acc[mt][nt][0] + bi0; o0.y = acc[mt][nt][1] + bi0;
            float2 o1; o1.x = acc[mt][nt][2] + bi1; o1.y = acc[mt][nt][3] + bi1;
            *(float2*)(outp + (size_t)row0 * ldo + col) = o0;
            *(float2*)(outp + (size_t)row1 * ldo + col) = o1;
        }
    }
}

// ---------------------------------------------------------------------------
// B: logits (tanh over H) + softmax; writes weights to out[WOFF..].
// Best-measured version: q-tile 4, grid 128, 1024 threads, h-split halves.
// ---------------------------------------------------------------------------
__global__ __launch_bounds__(1024)
void logits_softmax(const float* __restrict__ Maskp,
                    const float* __restrict__ Wo,
                    const float* __restrict__ bo_p,
                    float* __restrict__ out)
{
    const int blk  = blockIdx.x;       // 0..127
    const int b    = blk >> 4;
    const int q0   = (blk & 15) * 4;
    const int tid  = threadIdx.x;
    const int c    = tid & 511;
    const int half = tid >> 9;

    __shared__ float4 sh_rq[HH];
    __shared__ float  sh_wo[HH];
    __shared__ float4 sh_acc[CC];
    __shared__ float  sh_part[4][16];
    __shared__ float  sh_tot[4];

    if (tid < HH) {
        float4 r;
        r.x = g_resq[(b * QQ + q0 + 0) * HH + tid];
        r.y = g_resq[(b * QQ + q0 + 1) * HH + tid];
        r.z = g_resq[(b * QQ + q0 + 2) * HH + tid];
        r.w = g_resq[(b * QQ + q0 + 3) * HH + tid];
        sh_rq[tid] = r;
        sh_wo[tid] = Wo[tid];
    }
    __syncthreads();

    float a0 = 0.f, a1 = 0.f, a2 = 0.f, a3 = 0.f;
    {
        const int hbase = half << 7;
        const float* rc = g_rescT + (size_t)b * HH * CC + (size_t)hbase * CC + c;
        #pragma unroll 8
        for (int h = 0; h < 128; h++) {
            const float  a  = rc[(size_t)h * CC];
            const float4 rq = sh_rq[hbase + h];
            const float  w  = sh_wo[hbase + h];
            a0 += w * tanh_approx(a + rq.x);
            a1 += w * tanh_approx(a + rq.y);
            a2 += w * tanh_approx(a + rq.z);
            a3 += w * tanh_approx(a + rq.w);
        }
    }
    if (half == 0) {
        sh_acc[c] = make_float4(a0, a1, a2, a3);
    }
    __syncthreads();

    float e0, e1, e2, e3;
    if (half == 1) {
        const float4 p = sh_acc[c];
        const float bo = __ldg(bo_p);
        const float m  = Maskp[b * CC + c];
        e0 = m * __expf(a0 + p.x + bo);
        e1 = m * __expf(a1 + p.y + bo);
        e2 = m * __expf(a2 + p.z + bo);
        e3 = m * __expf(a3 + p.w + bo);

        float s0 = e0, s1 = e1, s2 = e2, s3 = e3;
        #pragma unroll
        for (int off = 16; off > 0; off >>= 1) {
            s0 += __shfl_xor_sync(0xffffffffu, s0, off);
            s1 += __shfl_xor_sync(0xffffffffu, s1, off);
            s2 += __shfl_xor_sync(0xffffffffu, s2, off);
            s3 += __shfl_xor_sync(0xffffffffu, s3, off);
        }
        const int lane = tid & 31, w2 = (tid >> 5) & 15;
        if (lane == 0) {
            sh_part[0][w2] = s0; sh_part[1][w2] = s1;
            sh_part[2][w2] = s2; sh_part[3][w2] = s3;
        }
    }
    __syncthreads();
    if (tid < 4) {
        float t = 0.f;
        #pragma unroll
        for (int i = 0; i < 16; i++) t += sh_part[tid][i];
        sh_tot[tid] = 1.f / (t + EPSF);
    }
    __syncthreads();

    if (half == 1) {
        out[WOFF + (b * QQ + q0 + 0) * CC + c] = e0 * sh_tot[0];
        out[WOFF + (b * QQ + q0 + 1) * CC + c] = e1 * sh_tot[1];
        out[WOFF + (b * QQ + q0 + 2) * CC + c] = e2 * sh_tot[2];
        out[WOFF + (b * QQ + q0 + 3) * CC + c] = e3 * sh_tot[3];
    }
}

// ---------------------------------------------------------------------------
// C: output[bq][d] = sum_c weights[bq][c] * ctx[b][c][d]
// cp.async 3-stage pipeline, K(=c)-tile 64. 128 blocks x 256 thr. (R14)
// ---------------------------------------------------------------------------
#define OG_LDW 68
#define OG_LDC 36
#define OG_WS_U (64 * OG_LDW)
#define OG_CS_U (64 * OG_LDC)
#define OG_STAGE_U (OG_WS_U + OG_CS_U)
#define OG_SMEM (NSTAGE * OG_STAGE_U * 4)  // 79872 B

__global__ __launch_bounds__(256, 1)
void out_gemm(const float* __restrict__ Ctx,
              const float* __restrict__ Wgt,
              float* __restrict__ out)
{
    extern __shared__ uint32_t smem[];
    const uint32_t smem_b = s2u(smem);

    const int blk = blockIdx.x;        // 0..127
    const int b   = blk >> 4;
    const int d0  = (blk & 15) * 32;
    const int tid = threadIdx.x;
    const int ty  = tid >> 4;
    const int tx  = tid & 15;

    const float* Wp = Wgt + (size_t)b * QQ * CC;
    const float* Cp = Ctx + (size_t)b * CC * DD + d0;

    int wq[4], wc[4], cc_[2], cd[2];
    #pragma unroll
    for (int i = 0; i < 4; i++) {
        const int f = tid + (i << 8);
        wq[i] = f >> 4;
        wc[i] = (f & 15) << 2;
    }
    #pragma unroll
    for (int i = 0; i < 2; i++) {
        const int f = tid + (i << 8);
        cc_[i] = f >> 3;
        cd[i]  = (f & 7) << 2;
    }

    auto issue_stage = [&](int buf, int kt) {
        const uint32_t base = smem_b + buf * (OG_STAGE_U * 4);
        #pragma unroll
        for (int i = 0; i < 4; i++)
            cp16(base + (wq[i] * OG_LDW + wc[i]) * 4,
                 Wp + (size_t)wq[i] * CC + kt + wc[i]);
        #pragma unroll
        for (int i = 0; i < 2; i++)
            cp16(base + (OG_WS_U + cc_[i] * OG_LDC + cd[i]) * 4,
                 Cp + (size_t)(kt + cc_[i]) * DD + cd[i]);
        asm volatile("cp.async.commit_group;" ::: "memory");
    };

    ull acc[4] = {};

    issue_stage(0, 0);
    issue_stage(1, 64);

    #pragma unroll 1
    for (int t = 0; t < 8; t++) {
        if (t < 6) {
            asm volatile("cp.async.wait_group 1;" ::: "memory");
        } else {
            asm volatile("cp.async.wait_group 0;" ::: "memory");
        }
        __syncthreads();

        if (t < 6) issue_stage((t + 2) % NSTAGE, (t + 2) * 64);

        const float* W_s = (const float*)(smem + (t % NSTAGE) * OG_STAGE_U);
        const float* C_s = W_s + OG_WS_U;
        #pragma unroll 8
        for (int cc = 0; cc < 64; cc++) {
            const ull cv = *(const ull*)&C_s[cc * OG_LDC + tx * 2];
            const float w0 = W_s[(ty * 4 + 0) * OG_LDW + cc];
            const float w1 = W_s[(ty * 4 + 1) * OG_LDW + cc];
            const float w2 = W_s[(ty * 4 + 2) * OG_LDW + cc];
            const float w3 = W_s[(ty * 4 + 3) * OG_LDW + cc];
            fma2(acc[0], pack2(w0), cv);
            fma2(acc[1], pack2(w1), cv);
            fma2(acc[2], pack2(w2), cv);
            fma2(acc[3], pack2(w3), cv);
        }
    }

    #pragma unroll
    for (int i = 0; i < 4; i++) {
        float2 p = unpack2(acc[i]);
        const int q = ty * 4 + i;
        *(float2*)&out[(b * QQ + q) * DD + d0 + tx * 2] = p;
    }
}

// ---------------------------------------------------------------------------
extern "C" void kernel_launch(void* const* d_in, const int* in_sizes, int n_in,
                              void* d_out, int out_size)
{
    const float* query   = (const float*)d_in[0];
    const float* context = (const float*)d_in[1];
    const float* mask    = (const float*)d_in[2];
    const float* W_c     = (const float*)d_in[3];
    const float* b_c     = (const float*)d_in[4];
    const float* W_q     = (const float*)d_in[5];
    const float* W_o     = (const float*)d_in[6];
    const float* b_o     = (const float*)d_in[7];
    float* out = (float*)d_out;

    cudaFuncSetAttribute(tc_gemms, cudaFuncAttributeMaxDynamicSharedMemorySize,
                         TCG_SMEM);
    cudaFuncSetAttribute(out_gemm, cudaFuncAttributeMaxDynamicSharedMemorySize,
                         OG_SMEM);

    tc_gemms<<<288, 256, TCG_SMEM>>>(W_c, context, b_c, query, W_q);
    logits_softmax<<<128, 1024>>>(mask, W_o, b_o, out);
    out_gemm<<<128, 256, OG_SMEM>>>(context, out + WOFF, out);
}